// round 10
// baseline (speedup 1.0000x reference)
#include <cuda_runtime.h>
#include <cuda_fp16.h>
#include <cstdint>

#define N_NODES_MAX 100000
#define DIM     64
#define MAX_SCAN_BLOCKS 256

// ---- scratch (allocation-free rule: __device__ globals) ----
__device__ __align__(256) __half g_y16[N_NODES_MAX * DIM];  // fp16 (feature*norm)@W^T
__device__ __align__(16) int g_count[N_NODES_MAX];          // per-dst degree (self-zeroing)
__device__ int g_offset[N_NODES_MAX];        // exclusive scan (PARTIAL per 1024-tile)
__device__ int g_sorted_src[2000000];        // src indices grouped by dst
__device__ int g_blocksums[MAX_SCAN_BLOCKS]; // scanned tile sums
__device__ int g_scan_ctr = 0;               // ticket; self-resets each run

// ---------------------------------------------------------------------------
// K1: y16 = fp16((feature * norm) @ W^T)  +  fused dst histogram
// (g_count zeroed by previous run's gather; globals start zeroed).
// Block = 256 = 64 nodes x 4 col-groups.
// ---------------------------------------------------------------------------
__global__ void __launch_bounds__(256)
transform_kernel(const float* __restrict__ feature,
                 const float* __restrict__ norm,
                 const float* __restrict__ W,
                 const int* __restrict__ dst,
                 int n, int e) {
    __shared__ float Wt[DIM * DIM];
    int tid = threadIdx.x;
    for (int k = tid; k < DIM * DIM; k += 256) {
        int j = k >> 6, i = k & 63;
        Wt[i * DIM + j] = W[k];
    }

    // fused histogram: grid-stride over edges
    int gid = blockIdx.x * 256 + tid;
    int stride = gridDim.x * 256;
    for (int i = gid; i < e; i += stride)
        atomicAdd(&g_count[__ldg(dst + i)], 1);

    __syncthreads();

    int node = blockIdx.x * 64 + (tid >> 2);
    int jg   = (tid & 3) * 16;
    if (node >= n) return;

    float nv = __ldg(norm + node);

    unsigned long long a01, a23, a45, a67, a89, aab, acd, aef;
    asm("mov.b64 %0, {%1, %1};" : "=l"(a01) : "f"(0.0f));
    a23 = a01; a45 = a01; a67 = a01; a89 = a01; aab = a01; acd = a01; aef = a01;

    const float4* arow = reinterpret_cast<const float4*>(feature + (size_t)node * DIM);
#pragma unroll
    for (int i4 = 0; i4 < 16; i4++) {
        float4 a = arow[i4];
        a.x *= nv; a.y *= nv; a.z *= nv; a.w *= nv;
        const float av[4] = {a.x, a.y, a.z, a.w};
#pragma unroll
        for (int c = 0; c < 4; c++) {
            int i = i4 * 4 + c;
            unsigned long long aa;
            asm("mov.b64 %0, {%1, %1};" : "=l"(aa) : "f"(av[c]));
            const ulonglong2* wp = reinterpret_cast<const ulonglong2*>(&Wt[i * DIM + jg]);
            ulonglong2 w0 = wp[0], w1 = wp[1];
            asm("fma.rn.f32x2 %0, %1, %2, %0;" : "+l"(a01) : "l"(aa), "l"(w0.x));
            asm("fma.rn.f32x2 %0, %1, %2, %0;" : "+l"(a23) : "l"(aa), "l"(w0.y));
            asm("fma.rn.f32x2 %0, %1, %2, %0;" : "+l"(a45) : "l"(aa), "l"(w1.x));
            asm("fma.rn.f32x2 %0, %1, %2, %0;" : "+l"(a67) : "l"(aa), "l"(w1.y));
            const ulonglong2* wq = reinterpret_cast<const ulonglong2*>(&Wt[i * DIM + jg + 8]);
            ulonglong2 w2 = wq[0], w3 = wq[1];
            asm("fma.rn.f32x2 %0, %1, %2, %0;" : "+l"(a89) : "l"(aa), "l"(w2.x));
            asm("fma.rn.f32x2 %0, %1, %2, %0;" : "+l"(aab) : "l"(aa), "l"(w2.y));
            asm("fma.rn.f32x2 %0, %1, %2, %0;" : "+l"(acd) : "l"(aa), "l"(w3.x));
            asm("fma.rn.f32x2 %0, %1, %2, %0;" : "+l"(aef) : "l"(aa), "l"(w3.y));
        }
    }

    float r[16];
    asm("mov.b64 {%0, %1}, %2;" : "=f"(r[0]), "=f"(r[1]) : "l"(a01));
    asm("mov.b64 {%0, %1}, %2;" : "=f"(r[2]), "=f"(r[3]) : "l"(a23));
    asm("mov.b64 {%0, %1}, %2;" : "=f"(r[4]), "=f"(r[5]) : "l"(a45));
    asm("mov.b64 {%0, %1}, %2;" : "=f"(r[6]), "=f"(r[7]) : "l"(a67));
    asm("mov.b64 {%0, %1}, %2;" : "=f"(r[8]), "=f"(r[9]) : "l"(a89));
    asm("mov.b64 {%0, %1}, %2;" : "=f"(r[10]), "=f"(r[11]) : "l"(aab));
    asm("mov.b64 {%0, %1}, %2;" : "=f"(r[12]), "=f"(r[13]) : "l"(acd));
    asm("mov.b64 {%0, %1}, %2;" : "=f"(r[14]), "=f"(r[15]) : "l"(aef));

    uint4 p0, p1;
    __half2 h;
    h = __floats2half2_rn(r[0],  r[1]);  p0.x = *reinterpret_cast<uint32_t*>(&h);
    h = __floats2half2_rn(r[2],  r[3]);  p0.y = *reinterpret_cast<uint32_t*>(&h);
    h = __floats2half2_rn(r[4],  r[5]);  p0.z = *reinterpret_cast<uint32_t*>(&h);
    h = __floats2half2_rn(r[6],  r[7]);  p0.w = *reinterpret_cast<uint32_t*>(&h);
    h = __floats2half2_rn(r[8],  r[9]);  p1.x = *reinterpret_cast<uint32_t*>(&h);
    h = __floats2half2_rn(r[10], r[11]); p1.y = *reinterpret_cast<uint32_t*>(&h);
    h = __floats2half2_rn(r[12], r[13]); p1.z = *reinterpret_cast<uint32_t*>(&h);
    h = __floats2half2_rn(r[14], r[15]); p1.w = *reinterpret_cast<uint32_t*>(&h);
    uint4* yp = reinterpret_cast<uint4*>(g_y16 + (size_t)node * DIM + jg);
    yp[0] = p0;
    yp[1] = p1;
}

// ---------------------------------------------------------------------------
// K2: shfl-based scan (256 threads x 4 elems); last block finalizes tile sums.
// ---------------------------------------------------------------------------
__global__ void __launch_bounds__(256) scan_kernel(int n, int nb) {
    __shared__ int warp_sums[8];
    __shared__ int sh2[MAX_SCAN_BLOCKS];
    __shared__ int is_last;
    int tid  = threadIdx.x;
    int lane = tid & 31, wid = tid >> 5;
    int base = blockIdx.x * 1024 + tid * 4;

    int4 v = make_int4(0, 0, 0, 0);
    if (base + 3 < n) {
        v = *reinterpret_cast<const int4*>(g_count + base);
    } else {
        if (base + 0 < n) v.x = g_count[base + 0];
        if (base + 1 < n) v.y = g_count[base + 1];
        if (base + 2 < n) v.z = g_count[base + 2];
        if (base + 3 < n) v.w = g_count[base + 3];
    }
    int s1 = v.x + v.y, s2 = s1 + v.z, s3 = s2 + v.w;
    int tsum = s3;

    int p = tsum;
#pragma unroll
    for (int d = 1; d < 32; d <<= 1) {
        int t = __shfl_up_sync(0xffffffffu, p, d);
        if (lane >= d) p += t;
    }
    if (lane == 31) warp_sums[wid] = p;
    __syncthreads();
    if (wid == 0 && lane < 8) {
        int w = warp_sums[lane];
        int q = w;
#pragma unroll
        for (int d = 1; d < 8; d <<= 1) {
            int t = __shfl_up_sync(0xffu, q, d);
            if (lane >= d) q += t;
        }
        warp_sums[lane] = q - w;
    }
    __syncthreads();

    int excl = warp_sums[wid] + (p - tsum);
    if (base + 0 < n) g_offset[base + 0] = excl;
    if (base + 1 < n) g_offset[base + 1] = excl + v.x;
    if (base + 2 < n) g_offset[base + 2] = excl + s1;
    if (base + 3 < n) g_offset[base + 3] = excl + s2;
    if (tid == 255) g_blocksums[blockIdx.x] = excl + tsum;

    __threadfence();
    if (tid == 0) is_last = (atomicAdd(&g_scan_ctr, 1) == gridDim.x - 1);
    __syncthreads();
    if (!is_last) return;
    __threadfence();
    int w = (tid < nb) ? g_blocksums[tid] : 0;
    sh2[tid] = w;
    __syncthreads();
#pragma unroll
    for (int d = 1; d < MAX_SCAN_BLOCKS; d <<= 1) {
        int t = (tid >= d) ? sh2[tid - d] : 0;
        __syncthreads();
        sh2[tid] += t;
        __syncthreads();
    }
    if (tid < nb) g_blocksums[tid] = sh2[tid] - w;
    if (tid == 0) g_scan_ctr = 0;
}

// ---------------------------------------------------------------------------
// K3: bucket fill, 4 edges/thread via int4 loads -> 4 independent atomic
// chains in flight (latency hiding).
// ---------------------------------------------------------------------------
__global__ void __launch_bounds__(256)
fill_kernel(const int* __restrict__ src,
            const int* __restrict__ dst, int e) {
    int i = (blockIdx.x * 256 + threadIdx.x) * 4;
    if (i + 4 <= e) {
        int4 d4 = __ldg(reinterpret_cast<const int4*>(dst + i));
        int4 s4 = __ldg(reinterpret_cast<const int4*>(src + i));
        int p0 = atomicAdd(&g_offset[d4.x], 1);
        int p1 = atomicAdd(&g_offset[d4.y], 1);
        int p2 = atomicAdd(&g_offset[d4.z], 1);
        int p3 = atomicAdd(&g_offset[d4.w], 1);
        g_sorted_src[p0 + __ldg(g_blocksums + (d4.x >> 10))] = s4.x;
        g_sorted_src[p1 + __ldg(g_blocksums + (d4.y >> 10))] = s4.y;
        g_sorted_src[p2 + __ldg(g_blocksums + (d4.z >> 10))] = s4.z;
        g_sorted_src[p3 + __ldg(g_blocksums + (d4.w >> 10))] = s4.w;
    } else {
        for (; i < e; i++) {
            int d = __ldg(dst + i);
            int p = atomicAdd(&g_offset[d], 1);
            g_sorted_src[p + __ldg(g_blocksums + (d >> 10))] = __ldg(src + i);
        }
    }
}

// ---------------------------------------------------------------------------
// K4: gather-accumulate + epilogue. ONE WARP PER DST NODE, 2 edges/warp-LDG;
// full pairwise fp16 tree (quad-combine) before one fp32 accumulate.
// Also zeroes g_count[node] for the next graph replay (replaces memset node).
// out[node] = norm[node] * sum(y16[src]) + b.
// ---------------------------------------------------------------------------
__device__ __forceinline__ void acc_h16(float4& a, uint2 v) {
    float2 lo = __half22float2(*reinterpret_cast<__half2*>(&v.x));
    float2 hi = __half22float2(*reinterpret_cast<__half2*>(&v.y));
    a.x += lo.x; a.y += lo.y; a.z += hi.x; a.w += hi.y;
}
__device__ __forceinline__ uint2 h2add(uint2 a, uint2 b) {
    uint2 r;
    asm("add.rn.f16x2 %0, %1, %2;" : "=r"(r.x) : "r"(a.x), "r"(b.x));
    asm("add.rn.f16x2 %0, %1, %2;" : "=r"(r.y) : "r"(a.y), "r"(b.y));
    return r;
}

__global__ void __launch_bounds__(256)
gather_kernel(const float* __restrict__ norm,
              const float* __restrict__ b,
              float* __restrict__ out, int n) {
    int node = blockIdx.x * 8 + (threadIdx.x >> 5);
    int lane = threadIdx.x & 31;
    if (node >= n) return;
    int half = lane >> 4;     // which edge of the pair
    int c16  = lane & 15;     // 8-byte chunk within the 128 B row

    int deg = __ldg(g_count + node);
    int end = __ldg(g_offset + node) + __ldg(g_blocksums + (node >> 10));
    int k   = end - deg;

    // zero the histogram slot for the next replay (replaces cudaMemset node)
    if (lane == 0) g_count[node] = 0;

    const uint2* __restrict__ y2 = reinterpret_cast<const uint2*>(g_y16);

    float4 acc0 = make_float4(0.f, 0.f, 0.f, 0.f);
    float4 acc1 = make_float4(0.f, 0.f, 0.f, 0.f);

    // 8 edges (4 pairs) per iteration: full fp16 quad tree, single fp32 acc
    for (; k + 8 <= end; k += 8) {
        int s0 = __ldg(g_sorted_src + k + 0 + half);
        int s1 = __ldg(g_sorted_src + k + 2 + half);
        int s2 = __ldg(g_sorted_src + k + 4 + half);
        int s3 = __ldg(g_sorted_src + k + 6 + half);
        uint2 v0 = __ldg(y2 + (size_t)s0 * 16 + c16);
        uint2 v1 = __ldg(y2 + (size_t)s1 * 16 + c16);
        uint2 v2 = __ldg(y2 + (size_t)s2 * 16 + c16);
        uint2 v3 = __ldg(y2 + (size_t)s3 * 16 + c16);
        acc_h16(acc0, h2add(h2add(v0, v1), h2add(v2, v3)));
    }
    // 4-edge tail (2 pairs -> one fp16 combine)
    if (k + 4 <= end) {
        int s0 = __ldg(g_sorted_src + k + 0 + half);
        int s1 = __ldg(g_sorted_src + k + 2 + half);
        uint2 v0 = __ldg(y2 + (size_t)s0 * 16 + c16);
        uint2 v1 = __ldg(y2 + (size_t)s1 * 16 + c16);
        acc_h16(acc1, h2add(v0, v1));
        k += 4;
    }
    // pair tail
    if (k + 2 <= end) {
        int s = __ldg(g_sorted_src + k + half);
        uint2 v = __ldg(y2 + (size_t)s * 16 + c16);
        acc_h16(acc0, v);
        k += 2;
    }
    // single leftover edge (half-0 lanes only)
    if (k < end && half == 0) {
        int s = __ldg(g_sorted_src + k);
        uint2 v = __ldg(y2 + (size_t)s * 16 + c16);
        acc_h16(acc1, v);
    }

    acc0.x += acc1.x; acc0.y += acc1.y; acc0.z += acc1.z; acc0.w += acc1.w;

    acc0.x += __shfl_xor_sync(0xffffffffu, acc0.x, 16);
    acc0.y += __shfl_xor_sync(0xffffffffu, acc0.y, 16);
    acc0.z += __shfl_xor_sync(0xffffffffu, acc0.z, 16);
    acc0.w += __shfl_xor_sync(0xffffffffu, acc0.w, 16);

    if (half == 0) {
        float nv = __ldg(norm + node);
        float4 bv = reinterpret_cast<const float4*>(b)[c16];
        acc0.x = fmaf(acc0.x, nv, bv.x);
        acc0.y = fmaf(acc0.y, nv, bv.y);
        acc0.z = fmaf(acc0.z, nv, bv.z);
        acc0.w = fmaf(acc0.w, nv, bv.w);
        reinterpret_cast<float4*>(out + (size_t)node * DIM)[c16] = acc0;
    }
}

// ---------------------------------------------------------------------------
// Launch. Inputs: 0 feature [N,64] f32, 1 norm [N] f32, 2 src [E] i32,
//                 3 dst [E] i32, 4 W [64,64] f32, 5 b [64] f32. out [N,64] f32.
// ---------------------------------------------------------------------------
extern "C" void kernel_launch(void* const* d_in, const int* in_sizes, int n_in,
                              void* d_out, int out_size) {
    const float* feature = (const float*)d_in[0];
    const float* norm    = (const float*)d_in[1];
    const int*   src     = (const int*)d_in[2];
    const int*   dst     = (const int*)d_in[3];
    const float* W       = (const float*)d_in[4];
    const float* b       = (const float*)d_in[5];
    float*       out     = (float*)d_out;

    int n = in_sizes[1];
    int e = in_sizes[2];

    transform_kernel<<<(n + 63) / 64, 256>>>(feature, norm, W, dst, n, e);

    int nb = (n + 1023) / 1024;
    scan_kernel<<<nb, 256>>>(n, nb);

    int fill_threads = (e + 3) / 4;
    fill_kernel<<<(fill_threads + 255) / 256, 256>>>(src, dst, e);

    gather_kernel<<<(n + 7) / 8, 256>>>(norm, b, out, n);
}

// round 11
// speedup vs baseline: 1.9452x; 1.9452x over previous
#include <cuda_runtime.h>
#include <cuda_fp16.h>
#include <cstdint>

#define N_NODES_MAX 100000
#define DIM     64
#define MAX_SCAN_BLOCKS 256

// ---- scratch (allocation-free rule: __device__ globals) ----
__device__ __align__(256) __half g_y16[N_NODES_MAX * DIM];  // fp16 (feature*norm)@W^T
__device__ __align__(16) int g_count[N_NODES_MAX];          // per-dst degree
__device__ int g_offset[N_NODES_MAX];        // exclusive scan (PARTIAL per 1024-tile)
__device__ int g_sorted_src[2000000];        // src indices grouped by dst
__device__ int g_blocksums[MAX_SCAN_BLOCKS]; // scanned tile sums
__device__ int g_scan_ctr = 0;               // ticket; self-resets each run

// ---------------------------------------------------------------------------
// K1: y16 = fp16((feature * norm) @ W^T)  +  fused dst histogram
// (g_count pre-zeroed by memset node). Block = 256 = 64 nodes x 4 col-groups.
// ---------------------------------------------------------------------------
__global__ void __launch_bounds__(256)
transform_kernel(const float* __restrict__ feature,
                 const float* __restrict__ norm,
                 const float* __restrict__ W,
                 const int* __restrict__ dst,
                 int n, int e) {
    __shared__ float Wt[DIM * DIM];
    int tid = threadIdx.x;
    for (int k = tid; k < DIM * DIM; k += 256) {
        int j = k >> 6, i = k & 63;
        Wt[i * DIM + j] = W[k];
    }

    // fused histogram: grid-stride over edges
    int gid = blockIdx.x * 256 + tid;
    int stride = gridDim.x * 256;
    for (int i = gid; i < e; i += stride)
        atomicAdd(&g_count[__ldg(dst + i)], 1);

    __syncthreads();

    int node = blockIdx.x * 64 + (tid >> 2);
    int jg   = (tid & 3) * 16;
    if (node >= n) return;

    float nv = __ldg(norm + node);

    unsigned long long a01, a23, a45, a67, a89, aab, acd, aef;
    asm("mov.b64 %0, {%1, %1};" : "=l"(a01) : "f"(0.0f));
    a23 = a01; a45 = a01; a67 = a01; a89 = a01; aab = a01; acd = a01; aef = a01;

    const float4* arow = reinterpret_cast<const float4*>(feature + (size_t)node * DIM);
#pragma unroll
    for (int i4 = 0; i4 < 16; i4++) {
        float4 a = arow[i4];
        a.x *= nv; a.y *= nv; a.z *= nv; a.w *= nv;
        const float av[4] = {a.x, a.y, a.z, a.w};
#pragma unroll
        for (int c = 0; c < 4; c++) {
            int i = i4 * 4 + c;
            unsigned long long aa;
            asm("mov.b64 %0, {%1, %1};" : "=l"(aa) : "f"(av[c]));
            const ulonglong2* wp = reinterpret_cast<const ulonglong2*>(&Wt[i * DIM + jg]);
            ulonglong2 w0 = wp[0], w1 = wp[1];
            asm("fma.rn.f32x2 %0, %1, %2, %0;" : "+l"(a01) : "l"(aa), "l"(w0.x));
            asm("fma.rn.f32x2 %0, %1, %2, %0;" : "+l"(a23) : "l"(aa), "l"(w0.y));
            asm("fma.rn.f32x2 %0, %1, %2, %0;" : "+l"(a45) : "l"(aa), "l"(w1.x));
            asm("fma.rn.f32x2 %0, %1, %2, %0;" : "+l"(a67) : "l"(aa), "l"(w1.y));
            const ulonglong2* wq = reinterpret_cast<const ulonglong2*>(&Wt[i * DIM + jg + 8]);
            ulonglong2 w2 = wq[0], w3 = wq[1];
            asm("fma.rn.f32x2 %0, %1, %2, %0;" : "+l"(a89) : "l"(aa), "l"(w2.x));
            asm("fma.rn.f32x2 %0, %1, %2, %0;" : "+l"(aab) : "l"(aa), "l"(w2.y));
            asm("fma.rn.f32x2 %0, %1, %2, %0;" : "+l"(acd) : "l"(aa), "l"(w3.x));
            asm("fma.rn.f32x2 %0, %1, %2, %0;" : "+l"(aef) : "l"(aa), "l"(w3.y));
        }
    }

    float r[16];
    asm("mov.b64 {%0, %1}, %2;" : "=f"(r[0]), "=f"(r[1]) : "l"(a01));
    asm("mov.b64 {%0, %1}, %2;" : "=f"(r[2]), "=f"(r[3]) : "l"(a23));
    asm("mov.b64 {%0, %1}, %2;" : "=f"(r[4]), "=f"(r[5]) : "l"(a45));
    asm("mov.b64 {%0, %1}, %2;" : "=f"(r[6]), "=f"(r[7]) : "l"(a67));
    asm("mov.b64 {%0, %1}, %2;" : "=f"(r[8]), "=f"(r[9]) : "l"(a89));
    asm("mov.b64 {%0, %1}, %2;" : "=f"(r[10]), "=f"(r[11]) : "l"(aab));
    asm("mov.b64 {%0, %1}, %2;" : "=f"(r[12]), "=f"(r[13]) : "l"(acd));
    asm("mov.b64 {%0, %1}, %2;" : "=f"(r[14]), "=f"(r[15]) : "l"(aef));

    uint4 p0, p1;
    __half2 h;
    h = __floats2half2_rn(r[0],  r[1]);  p0.x = *reinterpret_cast<uint32_t*>(&h);
    h = __floats2half2_rn(r[2],  r[3]);  p0.y = *reinterpret_cast<uint32_t*>(&h);
    h = __floats2half2_rn(r[4],  r[5]);  p0.z = *reinterpret_cast<uint32_t*>(&h);
    h = __floats2half2_rn(r[6],  r[7]);  p0.w = *reinterpret_cast<uint32_t*>(&h);
    h = __floats2half2_rn(r[8],  r[9]);  p1.x = *reinterpret_cast<uint32_t*>(&h);
    h = __floats2half2_rn(r[10], r[11]); p1.y = *reinterpret_cast<uint32_t*>(&h);
    h = __floats2half2_rn(r[12], r[13]); p1.z = *reinterpret_cast<uint32_t*>(&h);
    h = __floats2half2_rn(r[14], r[15]); p1.w = *reinterpret_cast<uint32_t*>(&h);
    uint4* yp = reinterpret_cast<uint4*>(g_y16 + (size_t)node * DIM + jg);
    yp[0] = p0;
    yp[1] = p1;
}

// ---------------------------------------------------------------------------
// K2: shfl-based scan (256 threads x 4 elems); last block finalizes tile sums.
// ---------------------------------------------------------------------------
__global__ void __launch_bounds__(256) scan_kernel(int n, int nb) {
    __shared__ int warp_sums[8];
    __shared__ int sh2[MAX_SCAN_BLOCKS];
    __shared__ int is_last;
    int tid  = threadIdx.x;
    int lane = tid & 31, wid = tid >> 5;
    int base = blockIdx.x * 1024 + tid * 4;

    int4 v = make_int4(0, 0, 0, 0);
    if (base + 3 < n) {
        v = *reinterpret_cast<const int4*>(g_count + base);
    } else {
        if (base + 0 < n) v.x = g_count[base + 0];
        if (base + 1 < n) v.y = g_count[base + 1];
        if (base + 2 < n) v.z = g_count[base + 2];
        if (base + 3 < n) v.w = g_count[base + 3];
    }
    int s1 = v.x + v.y, s2 = s1 + v.z, s3 = s2 + v.w;
    int tsum = s3;

    int p = tsum;
#pragma unroll
    for (int d = 1; d < 32; d <<= 1) {
        int t = __shfl_up_sync(0xffffffffu, p, d);
        if (lane >= d) p += t;
    }
    if (lane == 31) warp_sums[wid] = p;
    __syncthreads();
    if (wid == 0 && lane < 8) {
        int w = warp_sums[lane];
        int q = w;
#pragma unroll
        for (int d = 1; d < 8; d <<= 1) {
            int t = __shfl_up_sync(0xffu, q, d);
            if (lane >= d) q += t;
        }
        warp_sums[lane] = q - w;
    }
    __syncthreads();

    int excl = warp_sums[wid] + (p - tsum);
    if (base + 0 < n) g_offset[base + 0] = excl;
    if (base + 1 < n) g_offset[base + 1] = excl + v.x;
    if (base + 2 < n) g_offset[base + 2] = excl + s1;
    if (base + 3 < n) g_offset[base + 3] = excl + s2;
    if (tid == 255) g_blocksums[blockIdx.x] = excl + tsum;

    __threadfence();
    if (tid == 0) is_last = (atomicAdd(&g_scan_ctr, 1) == gridDim.x - 1);
    __syncthreads();
    if (!is_last) return;
    __threadfence();
    int w = (tid < nb) ? g_blocksums[tid] : 0;
    sh2[tid] = w;
    __syncthreads();
#pragma unroll
    for (int d = 1; d < MAX_SCAN_BLOCKS; d <<= 1) {
        int t = (tid >= d) ? sh2[tid - d] : 0;
        __syncthreads();
        sh2[tid] += t;
        __syncthreads();
    }
    if (tid < nb) g_blocksums[tid] = sh2[tid] - w;
    if (tid == 0) g_scan_ctr = 0;
}

// ---------------------------------------------------------------------------
// K3: bucket fill, 4 edges/thread via int4 loads -> 4 independent atomic
// chains in flight (latency hiding).
// ---------------------------------------------------------------------------
__global__ void __launch_bounds__(256)
fill_kernel(const int* __restrict__ src,
            const int* __restrict__ dst, int e) {
    int i = (blockIdx.x * 256 + threadIdx.x) * 4;
    if (i + 4 <= e) {
        int4 d4 = __ldg(reinterpret_cast<const int4*>(dst + i));
        int4 s4 = __ldg(reinterpret_cast<const int4*>(src + i));
        int p0 = atomicAdd(&g_offset[d4.x], 1);
        int p1 = atomicAdd(&g_offset[d4.y], 1);
        int p2 = atomicAdd(&g_offset[d4.z], 1);
        int p3 = atomicAdd(&g_offset[d4.w], 1);
        g_sorted_src[p0 + __ldg(g_blocksums + (d4.x >> 10))] = s4.x;
        g_sorted_src[p1 + __ldg(g_blocksums + (d4.y >> 10))] = s4.y;
        g_sorted_src[p2 + __ldg(g_blocksums + (d4.z >> 10))] = s4.z;
        g_sorted_src[p3 + __ldg(g_blocksums + (d4.w >> 10))] = s4.w;
    } else {
        for (; i < e; i++) {
            int d = __ldg(dst + i);
            int p = atomicAdd(&g_offset[d], 1);
            g_sorted_src[p + __ldg(g_blocksums + (d >> 10))] = __ldg(src + i);
        }
    }
}

// ---------------------------------------------------------------------------
// K4: gather-accumulate + epilogue. ONE WARP PER DST NODE, 2 edges/warp-LDG;
// full pairwise fp16 tree (quad-combine) before one fp32 accumulate.
// out[node] = norm[node] * sum(y16[src]) + b.
// ---------------------------------------------------------------------------
__device__ __forceinline__ void acc_h16(float4& a, uint2 v) {
    float2 lo = __half22float2(*reinterpret_cast<__half2*>(&v.x));
    float2 hi = __half22float2(*reinterpret_cast<__half2*>(&v.y));
    a.x += lo.x; a.y += lo.y; a.z += hi.x; a.w += hi.y;
}
__device__ __forceinline__ uint2 h2add(uint2 a, uint2 b) {
    uint2 r;
    asm("add.rn.f16x2 %0, %1, %2;" : "=r"(r.x) : "r"(a.x), "r"(b.x));
    asm("add.rn.f16x2 %0, %1, %2;" : "=r"(r.y) : "r"(a.y), "r"(b.y));
    return r;
}

__global__ void __launch_bounds__(256)
gather_kernel(const float* __restrict__ norm,
              const float* __restrict__ b,
              float* __restrict__ out, int n) {
    int node = blockIdx.x * 8 + (threadIdx.x >> 5);
    int lane = threadIdx.x & 31;
    if (node >= n) return;
    int half = lane >> 4;     // which edge of the pair
    int c16  = lane & 15;     // 8-byte chunk within the 128 B row

    int deg = __ldg(g_count + node);
    int end = __ldg(g_offset + node) + __ldg(g_blocksums + (node >> 10));
    int k   = end - deg;

    const uint2* __restrict__ y2 = reinterpret_cast<const uint2*>(g_y16);

    float4 acc0 = make_float4(0.f, 0.f, 0.f, 0.f);
    float4 acc1 = make_float4(0.f, 0.f, 0.f, 0.f);

    // 8 edges (4 pairs) per iteration: full fp16 quad tree, single fp32 acc
    for (; k + 8 <= end; k += 8) {
        int s0 = __ldg(g_sorted_src + k + 0 + half);
        int s1 = __ldg(g_sorted_src + k + 2 + half);
        int s2 = __ldg(g_sorted_src + k + 4 + half);
        int s3 = __ldg(g_sorted_src + k + 6 + half);
        uint2 v0 = __ldg(y2 + (size_t)s0 * 16 + c16);
        uint2 v1 = __ldg(y2 + (size_t)s1 * 16 + c16);
        uint2 v2 = __ldg(y2 + (size_t)s2 * 16 + c16);
        uint2 v3 = __ldg(y2 + (size_t)s3 * 16 + c16);
        acc_h16(acc0, h2add(h2add(v0, v1), h2add(v2, v3)));
    }
    // 4-edge tail (2 pairs -> one fp16 combine)
    if (k + 4 <= end) {
        int s0 = __ldg(g_sorted_src + k + 0 + half);
        int s1 = __ldg(g_sorted_src + k + 2 + half);
        uint2 v0 = __ldg(y2 + (size_t)s0 * 16 + c16);
        uint2 v1 = __ldg(y2 + (size_t)s1 * 16 + c16);
        acc_h16(acc1, h2add(v0, v1));
        k += 4;
    }
    // pair tail
    if (k + 2 <= end) {
        int s = __ldg(g_sorted_src + k + half);
        uint2 v = __ldg(y2 + (size_t)s * 16 + c16);
        acc_h16(acc0, v);
        k += 2;
    }
    // single leftover edge (half-0 lanes only)
    if (k < end && half == 0) {
        int s = __ldg(g_sorted_src + k);
        uint2 v = __ldg(y2 + (size_t)s * 16 + c16);
        acc_h16(acc1, v);
    }

    acc0.x += acc1.x; acc0.y += acc1.y; acc0.z += acc1.z; acc0.w += acc1.w;

    acc0.x += __shfl_xor_sync(0xffffffffu, acc0.x, 16);
    acc0.y += __shfl_xor_sync(0xffffffffu, acc0.y, 16);
    acc0.z += __shfl_xor_sync(0xffffffffu, acc0.z, 16);
    acc0.w += __shfl_xor_sync(0xffffffffu, acc0.w, 16);

    if (half == 0) {
        float nv = __ldg(norm + node);
        float4 bv = reinterpret_cast<const float4*>(b)[c16];
        acc0.x = fmaf(acc0.x, nv, bv.x);
        acc0.y = fmaf(acc0.y, nv, bv.y);
        acc0.z = fmaf(acc0.z, nv, bv.z);
        acc0.w = fmaf(acc0.w, nv, bv.w);
        reinterpret_cast<float4*>(out + (size_t)node * DIM)[c16] = acc0;
    }
}

// ---------------------------------------------------------------------------
// Launch. Inputs: 0 feature [N,64] f32, 1 norm [N] f32, 2 src [E] i32,
//                 3 dst [E] i32, 4 W [64,64] f32, 5 b [64] f32. out [N,64] f32.
// ---------------------------------------------------------------------------
extern "C" void kernel_launch(void* const* d_in, const int* in_sizes, int n_in,
                              void* d_out, int out_size) {
    const float* feature = (const float*)d_in[0];
    const float* norm    = (const float*)d_in[1];
    const int*   src     = (const int*)d_in[2];
    const int*   dst     = (const int*)d_in[3];
    const float* W       = (const float*)d_in[4];
    const float* b       = (const float*)d_in[5];
    float*       out     = (float*)d_out;

    int n = in_sizes[1];
    int e = in_sizes[2];

    void* count_ptr = nullptr;
    cudaGetSymbolAddress(&count_ptr, g_count);
    cudaMemsetAsync(count_ptr, 0, (size_t)n * sizeof(int));

    transform_kernel<<<(n + 63) / 64, 256>>>(feature, norm, W, dst, n, e);

    int nb = (n + 1023) / 1024;
    scan_kernel<<<nb, 256>>>(n, nb);

    int fill_threads = (e + 3) / 4;
    fill_kernel<<<(fill_threads + 255) / 256, 256>>>(src, dst, e);

    gather_kernel<<<(n + 7) / 8, 256>>>(norm, b, out, n);
}